// round 3
// baseline (speedup 1.0000x reference)
#include <cuda_runtime.h>
#include <cuda_bf16.h>
#include <mma.h>
#include <math.h>

using namespace nvcuda;

// Problem constants (match reference)
#define NT 16384      // tokens
#define DD 1024       // input dim
#define HH 2048       // hidden dim
#define EE 16         // experts
#define CAP 8192      // capacity = N / TOP_K
#define PADROWS (NT * 2 + EE * 128)   // compact rows padded to 128 per expert

// -------------------- device scratch (static, no allocs) --------------------
__device__ int   g_topk_idx[NT * 2];
__device__ float g_topk_w[NT * 2];
__device__ int   g_slotPos[NT * 2];       // rank within expert list, or -1 if dropped
__device__ int   g_tokList[EE * CAP];
__device__ int   g_cntFull[EE];
__device__ int   g_cntTrunc[EE];
__device__ int   g_offs[EE];              // 128-aligned compact offsets
__device__ float g_imp[EE];
__device__ float g_hid[(size_t)PADROWS * HH];    // ~285 MB hidden buffer
__device__ float g_out2[(size_t)PADROWS * DD];   // ~143 MB expert-output buffer

// -------------------- init --------------------
__global__ void init_kernel() {
    int t = threadIdx.x;
    if (t < EE) g_imp[t] = 0.0f;
}

// -------------------- router: logits, softmax, top-2, importance ------------
__global__ void router_kernel(const float* __restrict__ x,
                              const float* __restrict__ rw,
                              const float* __restrict__ rb) {
    __shared__ float simp[EE];
    int tid = threadIdx.x, lane = tid & 31, wid = tid >> 5;
    if (tid < EE) simp[tid] = 0.0f;
    __syncthreads();

    int tok = blockIdx.x * 8 + wid;
    int ex = lane & 15;
    int half = lane >> 4;
    const float* xr = x + (size_t)tok * DD;
    int k0 = half * 512;

    float a0 = 0.f, a1 = 0.f, a2 = 0.f, a3 = 0.f;
    #pragma unroll 4
    for (int k = 0; k < 512; k += 4) {
        a0 = fmaf(xr[k0 + k + 0], rw[(k0 + k + 0) * EE + ex], a0);
        a1 = fmaf(xr[k0 + k + 1], rw[(k0 + k + 1) * EE + ex], a1);
        a2 = fmaf(xr[k0 + k + 2], rw[(k0 + k + 2) * EE + ex], a2);
        a3 = fmaf(xr[k0 + k + 3], rw[(k0 + k + 3) * EE + ex], a3);
    }
    float acc = (a0 + a1) + (a2 + a3);
    acc += __shfl_xor_sync(0xffffffffu, acc, 16);
    float logit = acc + rb[ex];

    float mx = logit;
    #pragma unroll
    for (int o = 8; o >= 1; o >>= 1) mx = fmaxf(mx, __shfl_xor_sync(0xffffffffu, mx, o));
    float p = expf(logit - mx);
    float s = p;
    #pragma unroll
    for (int o = 8; o >= 1; o >>= 1) s += __shfl_xor_sync(0xffffffffu, s, o);
    float prob = p / s;

    if (half == 0) atomicAdd(&simp[ex], prob);

    float v = prob; int idx = ex;
    #pragma unroll
    for (int o = 8; o >= 1; o >>= 1) {
        float ov = __shfl_xor_sync(0xffffffffu, v, o);
        int   oi = __shfl_xor_sync(0xffffffffu, idx, o);
        if (ov > v || (ov == v && oi < idx)) { v = ov; idx = oi; }
    }
    int i0 = idx; float w0 = v;
    float v2 = (ex == i0) ? -1.0f : prob;
    int idx2 = (ex == i0) ? 1000 : ex;
    #pragma unroll
    for (int o = 8; o >= 1; o >>= 1) {
        float ov = __shfl_xor_sync(0xffffffffu, v2, o);
        int   oi = __shfl_xor_sync(0xffffffffu, idx2, o);
        if (ov > v2 || (ov == v2 && oi < idx2)) { v2 = ov; idx2 = oi; }
    }
    if (lane == 0) {
        g_topk_idx[2 * tok + 0] = i0;
        g_topk_idx[2 * tok + 1] = idx2;
        g_topk_w[2 * tok + 0] = w0;
        g_topk_w[2 * tok + 1] = v2;
    }
    __syncthreads();
    if (tid < EE) atomicAdd(&g_imp[tid], simp[tid]);
}

// -------------------- ordered per-expert compaction --------------------
__global__ void build_lists_kernel() {
    int e = blockIdx.x;
    int tid = threadIdx.x;            // 256
    int lane = tid & 31, wid = tid >> 5;
    __shared__ int wcnt[8];
    __shared__ int sbase;
    if (tid == 0) sbase = 0;
    __syncthreads();

    for (int chunk = 0; chunk < NT; chunk += 256) {
        int i = chunk + tid;
        int i0 = g_topk_idx[2 * i], i1 = g_topk_idx[2 * i + 1];
        bool m = (i0 == e) || (i1 == e);
        unsigned b = __ballot_sync(0xffffffffu, m);
        int wpre = __popc(b & ((1u << lane) - 1u));
        if (lane == 0) wcnt[wid] = __popc(b);
        __syncthreads();
        int woff = 0;
        #pragma unroll
        for (int w = 0; w < 8; w++) if (w < wid) woff += wcnt[w];
        int pos = sbase + woff + wpre;
        if (m) {
            int which = (i0 == e) ? 0 : 1;
            if (pos < CAP) {
                g_tokList[e * CAP + pos] = i;
                g_slotPos[2 * i + which] = pos;
            } else {
                g_slotPos[2 * i + which] = -1;
            }
        }
        __syncthreads();
        if (tid == 0) {
            int tot = 0;
            #pragma unroll
            for (int w = 0; w < 8; w++) tot += wcnt[w];
            sbase += tot;
        }
        __syncthreads();
    }
    if (tid == 0) {
        g_cntFull[e] = sbase;
        g_cntTrunc[e] = sbase < CAP ? sbase : CAP;
    }
}

// -------------------- offsets (128-padded) + aux loss --------------------
__global__ void finalize_kernel(float* __restrict__ d_out, long long out_size) {
    if (threadIdx.x == 0) {
        int off = 0;
        for (int e = 0; e < EE; e++) {
            g_offs[e] = off;
            off += (g_cntTrunc[e] + 127) & ~127;   // pad to 128 rows
        }
        float bal = 0.f, impl = 0.f;
        for (int e = 0; e < EE; e++) {
            float dens = g_imp[e] / (float)NT;
            float usage = (float)g_cntFull[e] / (float)NT;
            bal += dens * usage;
            impl += g_imp[e] * g_imp[e];
        }
        float aux = bal * (float)EE + impl / (float)EE;
        for (long long t = (long long)NT * DD; t < out_size; t++) d_out[t] = aux;
    }
}

// ======================= tf32 WMMA GEMMs ===================================
// Block tile 128x128, K-tile 32; 8 warps (4 in M x 2 in N), warp tile 32x64.
#define BM 128
#define BN 128
#define BK 32
#define ALD 40     // As leading dim (pad; multiple of 8)
#define BLD 136    // Bs leading dim (pad; multiple of 8)

// GEMM1: g_hid[base+m][n] = x[tokList[m]][:] @ w1[e][:,n]  (raw, bias+gelu later)
__global__ __launch_bounds__(256) void gemm1_kernel(const float* __restrict__ x,
                                                    const float* __restrict__ w1) {
    int e = blockIdx.z;
    int cnt = g_cntTrunc[e];
    int m0 = blockIdx.y * BM;
    if (m0 >= cnt) return;
    int n0 = blockIdx.x * BN;
    int base = g_offs[e];
    const float* B = w1 + (size_t)e * DD * HH;

    __shared__ float As[BM][ALD];
    __shared__ float Bs[BK][BLD];

    int tid = threadIdx.x;
    int wid = tid >> 5;
    int wm = wid & 3, wn = wid >> 2;

    // gathered row base pointers (clamped for padding rows)
    const float* aRow[4];
    #pragma unroll
    for (int i = 0; i < 4; i++) {
        int s = tid + i * 256;          // float4 slot id [0,1024)
        int r = s >> 3;                 // row 0..127
        int mg = m0 + r; if (mg >= cnt) mg = cnt - 1;
        aRow[i] = x + (size_t)g_tokList[e * CAP + mg] * DD + ((s & 7) * 4);
    }

    wmma::fragment<wmma::accumulator, 16, 16, 8, float> c[2][4];
    #pragma unroll
    for (int mi = 0; mi < 2; mi++)
        #pragma unroll
        for (int ni = 0; ni < 4; ni++) wmma::fill_fragment(c[mi][ni], 0.0f);

    for (int k0 = 0; k0 < DD; k0 += BK) {
        #pragma unroll
        for (int i = 0; i < 4; i++) {
            int s = tid + i * 256; int r = s >> 3; int cc = (s & 7) * 4;
            float4 av = *(const float4*)(aRow[i] + k0);
            As[r][cc + 0] = wmma::__float_to_tf32(av.x);
            As[r][cc + 1] = wmma::__float_to_tf32(av.y);
            As[r][cc + 2] = wmma::__float_to_tf32(av.z);
            As[r][cc + 3] = wmma::__float_to_tf32(av.w);
        }
        #pragma unroll
        for (int i = 0; i < 4; i++) {
            int s = tid + i * 256; int kr = s >> 5; int cc = (s & 31) * 4;
            float4 bv = *(const float4*)(B + (size_t)(k0 + kr) * HH + n0 + cc);
            Bs[kr][cc + 0] = wmma::__float_to_tf32(bv.x);
            Bs[kr][cc + 1] = wmma::__float_to_tf32(bv.y);
            Bs[kr][cc + 2] = wmma::__float_to_tf32(bv.z);
            Bs[kr][cc + 3] = wmma::__float_to_tf32(bv.w);
        }
        __syncthreads();
        #pragma unroll
        for (int kk = 0; kk < BK; kk += 8) {
            wmma::fragment<wmma::matrix_a, 16, 16, 8, wmma::precision::tf32, wmma::row_major> a[2];
            wmma::fragment<wmma::matrix_b, 16, 16, 8, wmma::precision::tf32, wmma::row_major> b[4];
            #pragma unroll
            for (int mi = 0; mi < 2; mi++)
                wmma::load_matrix_sync(a[mi], &As[wm * 32 + mi * 16][kk], ALD);
            #pragma unroll
            for (int ni = 0; ni < 4; ni++)
                wmma::load_matrix_sync(b[ni], &Bs[kk][wn * 64 + ni * 16], BLD);
            #pragma unroll
            for (int mi = 0; mi < 2; mi++)
                #pragma unroll
                for (int ni = 0; ni < 4; ni++)
                    wmma::mma_sync(c[mi][ni], a[mi], b[ni], c[mi][ni]);
        }
        __syncthreads();
    }

    // unguarded stores; expert regions are 128-row padded so overflow is harmless
    #pragma unroll
    for (int mi = 0; mi < 2; mi++) {
        int row0 = base + m0 + wm * 32 + mi * 16;
        #pragma unroll
        for (int ni = 0; ni < 4; ni++) {
            int col0 = n0 + wn * 64 + ni * 16;
            wmma::store_matrix_sync(g_hid + (size_t)row0 * HH + col0, c[mi][ni], HH,
                                    wmma::mem_row_major);
        }
    }
}

// bias + exact-erf GELU, in place on valid rows
__global__ void gelu_kernel(const float* __restrict__ b1) {
    int e = blockIdx.y;
    int m = blockIdx.x;
    if (m >= g_cntTrunc[e]) return;
    float* row = g_hid + (size_t)(g_offs[e] + m) * HH;
    const float* bias = b1 + (size_t)e * HH;
    int c = threadIdx.x * 8;
    #pragma unroll
    for (int j = 0; j < 2; j++) {
        float4 v = *(float4*)(row + c + j * 4);
        float4 bb = *(const float4*)(bias + c + j * 4);
        v.x += bb.x; v.y += bb.y; v.z += bb.z; v.w += bb.w;
        v.x = 0.5f * v.x * (1.0f + erff(v.x * 0.70710678118654752f));
        v.y = 0.5f * v.y * (1.0f + erff(v.y * 0.70710678118654752f));
        v.z = 0.5f * v.z * (1.0f + erff(v.z * 0.70710678118654752f));
        v.w = 0.5f * v.w * (1.0f + erff(v.w * 0.70710678118654752f));
        *(float4*)(row + c + j * 4) = v;
    }
}

// GEMM2: g_out2[base+m][n] = g_hid[base+m][:] @ w2[e][:,n]   (raw)
__global__ __launch_bounds__(256) void gemm2_kernel(const float* __restrict__ w2) {
    int e = blockIdx.z;
    int cnt = g_cntTrunc[e];
    int m0 = blockIdx.y * BM;
    if (m0 >= cnt) return;
    int n0 = blockIdx.x * BN;
    int base = g_offs[e];
    const float* B = w2 + (size_t)e * HH * DD;

    __shared__ float As[BM][ALD];
    __shared__ float Bs[BK][BLD];

    int tid = threadIdx.x;
    int wid = tid >> 5;
    int wm = wid & 3, wn = wid >> 2;

    const float* aRow[4];
    #pragma unroll
    for (int i = 0; i < 4; i++) {
        int s = tid + i * 256;
        int r = s >> 3;
        int mg = m0 + r; if (mg >= cnt) mg = cnt - 1;
        aRow[i] = g_hid + (size_t)(base + mg) * HH + ((s & 7) * 4);
    }

    wmma::fragment<wmma::accumulator, 16, 16, 8, float> c[2][4];
    #pragma unroll
    for (int mi = 0; mi < 2; mi++)
        #pragma unroll
        for (int ni = 0; ni < 4; ni++) wmma::fill_fragment(c[mi][ni], 0.0f);

    for (int k0 = 0; k0 < HH; k0 += BK) {
        #pragma unroll
        for (int i = 0; i < 4; i++) {
            int s = tid + i * 256; int r = s >> 3; int cc = (s & 7) * 4;
            float4 av = *(const float4*)(aRow[i] + k0);
            As[r][cc + 0] = wmma::__float_to_tf32(av.x);
            As[r][cc + 1] = wmma::__float_to_tf32(av.y);
            As[r][cc + 2] = wmma::__float_to_tf32(av.z);
            As[r][cc + 3] = wmma::__float_to_tf32(av.w);
        }
        #pragma unroll
        for (int i = 0; i < 4; i++) {
            int s = tid + i * 256; int kr = s >> 5; int cc = (s & 31) * 4;
            float4 bv = *(const float4*)(B + (size_t)(k0 + kr) * DD + n0 + cc);
            Bs[kr][cc + 0] = wmma::__float_to_tf32(bv.x);
            Bs[kr][cc + 1] = wmma::__float_to_tf32(bv.y);
            Bs[kr][cc + 2] = wmma::__float_to_tf32(bv.z);
            Bs[kr][cc + 3] = wmma::__float_to_tf32(bv.w);
        }
        __syncthreads();
        #pragma unroll
        for (int kk = 0; kk < BK; kk += 8) {
            wmma::fragment<wmma::matrix_a, 16, 16, 8, wmma::precision::tf32, wmma::row_major> a[2];
            wmma::fragment<wmma::matrix_b, 16, 16, 8, wmma::precision::tf32, wmma::row_major> b[4];
            #pragma unroll
            for (int mi = 0; mi < 2; mi++)
                wmma::load_matrix_sync(a[mi], &As[wm * 32 + mi * 16][kk], ALD);
            #pragma unroll
            for (int ni = 0; ni < 4; ni++)
                wmma::load_matrix_sync(b[ni], &Bs[kk][wn * 64 + ni * 16], BLD);
            #pragma unroll
            for (int mi = 0; mi < 2; mi++)
                #pragma unroll
                for (int ni = 0; ni < 4; ni++)
                    wmma::mma_sync(c[mi][ni], a[mi], b[ni], c[mi][ni]);
        }
        __syncthreads();
    }

    #pragma unroll
    for (int mi = 0; mi < 2; mi++) {
        int row0 = base + m0 + wm * 32 + mi * 16;
        #pragma unroll
        for (int ni = 0; ni < 4; ni++) {
            int col0 = n0 + wn * 64 + ni * 16;
            wmma::store_matrix_sync(g_out2 + (size_t)row0 * DD + col0, c[mi][ni], DD,
                                    wmma::mem_row_major);
        }
    }
}

// weighted gather: y[t] = sum over t's kept slots of w_tok * (out2[slot] + b2[e])
__global__ void gather_kernel(const float* __restrict__ b2, float* __restrict__ y) {
    int t = blockIdx.x;
    int e0 = g_topk_idx[2 * t], e1 = g_topk_idx[2 * t + 1];
    int p0 = g_slotPos[2 * t], p1 = g_slotPos[2 * t + 1];
    float w0 = g_topk_w[2 * t], w1 = g_topk_w[2 * t + 1];
    const float* r0 = (p0 >= 0) ? g_out2 + (size_t)(g_offs[e0] + p0) * DD : 0;
    const float* r1 = (p1 >= 0) ? g_out2 + (size_t)(g_offs[e1] + p1) * DD : 0;
    const float* bb0 = b2 + (size_t)e0 * DD;
    const float* bb1 = b2 + (size_t)e1 * DD;
    int c = threadIdx.x * 4;
    float4 out = make_float4(0.f, 0.f, 0.f, 0.f);
    if (r0) {
        float4 v = *(const float4*)(r0 + c);
        float4 bv = *(const float4*)(bb0 + c);
        out.x += w0 * (v.x + bv.x); out.y += w0 * (v.y + bv.y);
        out.z += w0 * (v.z + bv.z); out.w += w0 * (v.w + bv.w);
    }
    if (r1) {
        float4 v = *(const float4*)(r1 + c);
        float4 bv = *(const float4*)(bb1 + c);
        out.x += w1 * (v.x + bv.x); out.y += w1 * (v.y + bv.y);
        out.z += w1 * (v.z + bv.z); out.w += w1 * (v.w + bv.w);
    }
    *(float4*)(y + (size_t)t * DD + c) = out;
}

// -------------------- launch --------------------
extern "C" void kernel_launch(void* const* d_in, const int* in_sizes, int n_in,
                              void* d_out, int out_size) {
    const float* x   = (const float*)d_in[0];
    const float* rw  = (const float*)d_in[1];
    const float* rb  = (const float*)d_in[2];
    const float* w1  = (const float*)d_in[3];
    const float* b1  = (const float*)d_in[4];
    const float* w2  = (const float*)d_in[5];
    const float* b2  = (const float*)d_in[6];
    float* y = (float*)d_out;

    init_kernel<<<1, 32>>>();
    router_kernel<<<NT / 8, 256>>>(x, rw, rb);
    build_lists_kernel<<<EE, 256>>>();
    finalize_kernel<<<1, 32>>>(y, (long long)out_size);
    {
        dim3 grid(HH / BN, CAP / BM, EE);   // (16, 64, 16)
        gemm1_kernel<<<grid, 256>>>(x, w1);
    }
    {
        dim3 grid(CAP, EE);
        gelu_kernel<<<grid, 256>>>(b1);
    }
    {
        dim3 grid(DD / BN, CAP / BM, EE);   // (8, 64, 16)
        gemm2_kernel<<<grid, 256>>>(w2);
    }
    gather_kernel<<<NT, 256>>>(b2, y);
}